// round 1
// baseline (speedup 1.0000x reference)
#include <cuda_runtime.h>
#include <cuda_bf16.h>
#include <math.h>

// Problem constants
#define Bq   8
#define Sq   2048
#define Dq   256
#define Hq   4
#define Dh   64
#define Mq   (Bq * Sq)        // 16384 rows

// ---------------- scratch (device globals; no allocation allowed) ----------
__device__ float g_qkv[Mq * 3 * Dq];          // [16384, 768]
__device__ float g_q  [Bq * Hq * Sq * Dh];    // [B,H,S,Dh]
__device__ float g_k  [Bq * Hq * Sq * Dh];
__device__ float g_v  [Bq * Hq * Sq * Dh];
__device__ float g_ctx[Mq * Dq];              // [B,S,D]
__device__ float g_msg[Mq * Dq];
__device__ float g_cat[Mq * 2 * Dq];          // [16384, 512]
__device__ float g_y  [Mq * 2 * Dq];

// ---------------- generic SGEMM: C = A[M,K] @ W[N,K]^T + bias (+resid) -----
// BM=BN=64, BK=16, 256 threads, 4x4 microtile.
template <bool RES>
__global__ void sgemm_kernel(const float* __restrict__ A,
                             const float* __restrict__ W,
                             const float* __restrict__ bias,
                             const float* __restrict__ resid,
                             float* __restrict__ C,
                             int M, int N, int K) {
    __shared__ float As[16][64];
    __shared__ float Ws[16][64];
    const int bm = blockIdx.y * 64;
    const int bn = blockIdx.x * 64;
    const int tid = threadIdx.x;
    const int tx = tid & 15;
    const int ty = tid >> 4;

    float acc[4][4] = {};

    const int lr = tid >> 2;          // 0..63 (row of tile)
    const int lk = (tid & 3) * 4;     // 0,4,8,12 (k chunk)

    for (int k0 = 0; k0 < K; k0 += 16) {
        float4 va = *(const float4*)&A[(size_t)(bm + lr) * K + k0 + lk];
        float4 vw = *(const float4*)&W[(size_t)(bn + lr) * K + k0 + lk];
        As[lk + 0][lr] = va.x; As[lk + 1][lr] = va.y;
        As[lk + 2][lr] = va.z; As[lk + 3][lr] = va.w;
        Ws[lk + 0][lr] = vw.x; Ws[lk + 1][lr] = vw.y;
        Ws[lk + 2][lr] = vw.z; Ws[lk + 3][lr] = vw.w;
        __syncthreads();
#pragma unroll
        for (int kk = 0; kk < 16; kk++) {
            float4 a4 = *(const float4*)&As[kk][ty * 4];
            float4 b4 = *(const float4*)&Ws[kk][tx * 4];
            float a[4] = {a4.x, a4.y, a4.z, a4.w};
            float b[4] = {b4.x, b4.y, b4.z, b4.w};
#pragma unroll
            for (int i = 0; i < 4; i++)
#pragma unroll
                for (int j = 0; j < 4; j++)
                    acc[i][j] = fmaf(a[i], b[j], acc[i][j]);
        }
        __syncthreads();
    }

#pragma unroll
    for (int i = 0; i < 4; i++) {
        const int m = bm + ty * 4 + i;
#pragma unroll
        for (int j = 0; j < 4; j++) {
            const int n = bn + tx * 4 + j;
            float v = acc[i][j] + bias[n];
            if (RES) v += resid[(size_t)m * N + n];
            C[(size_t)m * N + n] = v;
        }
    }
}

// ---------------- RoPE + split qkv into Q,K,V [B,H,S,Dh] -------------------
// qkv layout per row: n = h*192 + d*3 + {q,k,v}.  Q prescaled by Dh^-0.5.
__global__ void rope_split_kernel(const float* __restrict__ qkv,
                                  const float* __restrict__ kp) {
    int idx = blockIdx.x * blockDim.x + threadIdx.x;   // one thread per pair
    // idx over (b, s, h, pair) : 8*2048*4*32
    const int p = idx & 31;
    const int h = (idx >> 5) & 3;
    const int s = (idx >> 7) & 2047;
    const int b = idx >> 18;
    const int d0 = p * 2;

    const float* src = qkv + ((size_t)(b * Sq + s)) * 768 + h * 192 + d0 * 3;
    float q0 = src[0], k0 = src[1], v0 = src[2];
    float q1 = src[3], k1 = src[4], v1 = src[5];

    const size_t kpo = ((size_t)b * Sq + s) * Dh + d0;
    float c0 = kp[kpo],                 c1 = kp[kpo + 1];
    float s0 = kp[(size_t)Bq * Sq * Dh + kpo];
    float s1 = kp[(size_t)Bq * Sq * Dh + kpo + 1];

    const float scale = 0.125f;  // 64^-0.5, fold into Q
    float qo0 = (q0 * c0 - q1 * s0) * scale;
    float qo1 = (q1 * c1 + q0 * s1) * scale;
    float ko0 = k0 * c0 - k1 * s0;
    float ko1 = k1 * c1 + k0 * s1;

    const size_t o = (((size_t)b * Hq + h) * Sq + s) * Dh + d0;
    g_q[o] = qo0; g_q[o + 1] = qo1;
    g_k[o] = ko0; g_k[o + 1] = ko1;
    g_v[o] = v0;  g_v[o + 1] = v1;
}

// ---------------- flash attention: 64x64 tiles, online softmax -------------
// Q,K,V: [B,H,S,64] (Q prescaled). Output ctx: [B,S,256] (D = h*64+d).
__global__ void flash_attn_kernel(const float* __restrict__ Q,
                                  const float* __restrict__ K,
                                  const float* __restrict__ V,
                                  float* __restrict__ ctx) {
    __shared__ float Qs[64][64];   // [d][r]
    __shared__ float Ks[64][64];   // [d][c]  (aliased as Ps[j][r] later)
    __shared__ float Vs[64][64];   // [j][d]

    const int b = blockIdx.z, h = blockIdx.y, it = blockIdx.x;
    const int tid = threadIdx.x;
    const int tx = tid & 15;       // output-col group
    const int ty = tid >> 4;       // output-row group
    const size_t base = (((size_t)b * Hq + h) * Sq) * (size_t)Dh;

    // load Q tile, transposed to [d][r]
    {
        const int r = tid >> 2;
        const int db = (tid & 3) * 16;
        const float* qp = Q + base + (size_t)(it * 64 + r) * Dh + db;
#pragma unroll
        for (int u = 0; u < 4; u++) {
            float4 v = *(const float4*)(qp + u * 4);
            Qs[db + u * 4 + 0][r] = v.x;
            Qs[db + u * 4 + 1][r] = v.y;
            Qs[db + u * 4 + 2][r] = v.z;
            Qs[db + u * 4 + 3][r] = v.w;
        }
    }

    float m_i[4], l_i[4], acc[4][4];
#pragma unroll
    for (int i = 0; i < 4; i++) {
        m_i[i] = -INFINITY; l_i[i] = 0.f;
#pragma unroll
        for (int j = 0; j < 4; j++) acc[i][j] = 0.f;
    }

    for (int jt = 0; jt < Sq / 64; jt++) {
        __syncthreads();   // prev-iter PV done (also covers Q-load on iter 0)
        {   // load K transposed [d][c], V natural [j][d]
            const int r = tid >> 2;
            const int db = (tid & 3) * 16;
            const float* kp2 = K + base + (size_t)(jt * 64 + r) * Dh + db;
            const float* vp  = V + base + (size_t)(jt * 64 + r) * Dh + db;
#pragma unroll
            for (int u = 0; u < 4; u++) {
                float4 v = *(const float4*)(kp2 + u * 4);
                Ks[db + u * 4 + 0][r] = v.x;
                Ks[db + u * 4 + 1][r] = v.y;
                Ks[db + u * 4 + 2][r] = v.z;
                Ks[db + u * 4 + 3][r] = v.w;
                *(float4*)&Vs[r][db + u * 4] = *(const float4*)(vp + u * 4);
            }
        }
        __syncthreads();

        // S tile = Q^T K   (scores already include Dh^-0.5 via Q prescale)
        float s[4][4] = {};
#pragma unroll
        for (int kk = 0; kk < 64; kk++) {
            float4 a4 = *(const float4*)&Qs[kk][ty * 4];
            float4 b4 = *(const float4*)&Ks[kk][tx * 4];
            float a[4] = {a4.x, a4.y, a4.z, a4.w};
            float bb[4] = {b4.x, b4.y, b4.z, b4.w};
#pragma unroll
            for (int i = 0; i < 4; i++)
#pragma unroll
                for (int j = 0; j < 4; j++)
                    s[i][j] = fmaf(a[i], bb[j], s[i][j]);
        }

        // online softmax over tx-lanes (16 consecutive lanes share a row)
#pragma unroll
        for (int i = 0; i < 4; i++) {
            float tmax = s[i][0];
#pragma unroll
            for (int j = 1; j < 4; j++) tmax = fmaxf(tmax, s[i][j]);
#pragma unroll
            for (int msk = 8; msk >= 1; msk >>= 1)
                tmax = fmaxf(tmax, __shfl_xor_sync(0xffffffffu, tmax, msk));
            const float mn = fmaxf(m_i[i], tmax);
            const float factor = __expf(m_i[i] - mn);
            float rs = 0.f;
#pragma unroll
            for (int j = 0; j < 4; j++) {
                s[i][j] = __expf(s[i][j] - mn);
                rs += s[i][j];
            }
#pragma unroll
            for (int msk = 8; msk >= 1; msk >>= 1)
                rs += __shfl_xor_sync(0xffffffffu, rs, msk);
            l_i[i] = l_i[i] * factor + rs;
            m_i[i] = mn;
#pragma unroll
            for (int j = 0; j < 4; j++) acc[i][j] *= factor;
        }

        __syncthreads();   // all threads done reading Ks for S
        // store P^T into Ks alias: Ps[j][r]
#pragma unroll
        for (int i = 0; i < 4; i++)
#pragma unroll
            for (int j = 0; j < 4; j++)
                Ks[tx * 4 + j][ty * 4 + i] = s[i][j];
        __syncthreads();

        // acc[r][d] += sum_j Ps[j][r] * Vs[j][d]
#pragma unroll
        for (int kk = 0; kk < 64; kk++) {
            float4 a4 = *(const float4*)&Ks[kk][ty * 4];
            float4 b4 = *(const float4*)&Vs[kk][tx * 4];
            float a[4] = {a4.x, a4.y, a4.z, a4.w};
            float bb[4] = {b4.x, b4.y, b4.z, b4.w};
#pragma unroll
            for (int i = 0; i < 4; i++)
#pragma unroll
                for (int j = 0; j < 4; j++)
                    acc[i][j] = fmaf(a[i], bb[j], acc[i][j]);
        }
    }

    // write ctx[b, i0+r, h*64 + d]
#pragma unroll
    for (int i = 0; i < 4; i++) {
        const float inv = 1.f / l_i[i];
        const int r = it * 64 + ty * 4 + i;
#pragma unroll
        for (int j = 0; j < 4; j++)
            ctx[((size_t)b * Sq + r) * Dq + h * Dh + tx * 4 + j] = acc[i][j] * inv;
    }
}

// ---------------- concat(desc, msg) -> cat [16384,512] ---------------------
__global__ void concat_kernel(const float* __restrict__ desc,
                              const float* __restrict__ msg) {
    int idx = blockIdx.x * blockDim.x + threadIdx.x;   // one float4 each
    const int m = idx >> 7;          // 128 float4 per row
    const int c4 = idx & 127;
    float4 v;
    if (c4 < 64) v = ((const float4*)desc)[(size_t)m * 64 + c4];
    else         v = ((const float4*)msg)[(size_t)m * 64 + (c4 - 64)];
    ((float4*)g_cat)[idx] = v;
}

// ---------------- LayerNorm(512) + exact GELU, in place on g_y -------------
__global__ void ln_gelu_kernel(const float* __restrict__ gamma,
                               const float* __restrict__ beta) {
    __shared__ float2 sh[8];
    const int m = blockIdx.x;
    float* row = g_y + (size_t)m * 512;
    const int t = threadIdx.x;

    float a = row[t], b = row[t + 256];
    float2 v = make_float2(a + b, a * a + b * b);
#pragma unroll
    for (int msk = 16; msk >= 1; msk >>= 1) {
        v.x += __shfl_xor_sync(0xffffffffu, v.x, msk);
        v.y += __shfl_xor_sync(0xffffffffu, v.y, msk);
    }
    const int lane = t & 31, w = t >> 5;
    if (lane == 0) sh[w] = v;
    __syncthreads();
    if (w == 0) {
        v = (lane < 8) ? sh[lane] : make_float2(0.f, 0.f);
#pragma unroll
        for (int msk = 4; msk >= 1; msk >>= 1) {
            v.x += __shfl_xor_sync(0xffffffffu, v.x, msk);
            v.y += __shfl_xor_sync(0xffffffffu, v.y, msk);
        }
        if (lane == 0) sh[0] = v;
    }
    __syncthreads();
    const float mu = sh[0].x * (1.f / 512.f);
    const float var = sh[0].y * (1.f / 512.f) - mu * mu;
    const float inv = rsqrtf(var + 1e-5f);

#pragma unroll
    for (int u = 0; u < 2; u++) {
        const int c = t + u * 256;
        float x = (row[c] - mu) * inv * gamma[c] + beta[c];
        row[c] = 0.5f * x * (1.f + erff(x * 0.70710678118654752440f));
    }
}

// ---------------- launch ----------------------------------------------------
extern "C" void kernel_launch(void* const* d_in, const int* in_sizes, int n_in,
                              void* d_out, int out_size) {
    const float* desc   = (const float*)d_in[0];
    const float* kp     = (const float*)d_in[1];
    const float* Wqkv_w = (const float*)d_in[2];
    const float* Wqkv_b = (const float*)d_in[3];
    const float* Wo_w   = (const float*)d_in[4];
    const float* Wo_b   = (const float*)d_in[5];
    const float* W1_w   = (const float*)d_in[6];
    const float* W1_b   = (const float*)d_in[7];
    const float* ln_g   = (const float*)d_in[8];
    const float* ln_b   = (const float*)d_in[9];
    const float* W2_w   = (const float*)d_in[10];
    const float* W2_b   = (const float*)d_in[11];
    float* out = (float*)d_out;

    void *p_qkv, *p_q, *p_k, *p_v, *p_ctx, *p_msg, *p_cat, *p_y;
    cudaGetSymbolAddress(&p_qkv, g_qkv);
    cudaGetSymbolAddress(&p_q,   g_q);
    cudaGetSymbolAddress(&p_k,   g_k);
    cudaGetSymbolAddress(&p_v,   g_v);
    cudaGetSymbolAddress(&p_ctx, g_ctx);
    cudaGetSymbolAddress(&p_msg, g_msg);
    cudaGetSymbolAddress(&p_cat, g_cat);
    cudaGetSymbolAddress(&p_y,   g_y);

    // 1) QKV = desc @ Wqkv^T + b   [16384,768]
    sgemm_kernel<false><<<dim3(768 / 64, Mq / 64), 256>>>(
        desc, Wqkv_w, Wqkv_b, nullptr, (float*)p_qkv, Mq, 768, Dq);

    // 2) RoPE + split into Q,K,V [B,H,S,Dh]
    rope_split_kernel<<<(Bq * Sq * Hq * 32) / 256, 256>>>((const float*)p_qkv, kp);

    // 3) flash attention -> ctx [B,S,D]
    flash_attn_kernel<<<dim3(Sq / 64, Hq, Bq), 256>>>(
        (const float*)p_q, (const float*)p_k, (const float*)p_v, (float*)p_ctx);

    // 4) message = ctx @ Wo^T + b
    sgemm_kernel<false><<<dim3(Dq / 64, Mq / 64), 256>>>(
        (const float*)p_ctx, Wo_w, Wo_b, nullptr, (float*)p_msg, Mq, Dq, Dq);

    // 5) cat = [desc, msg]
    concat_kernel<<<(Mq * 512 / 4) / 256, 256>>>(desc, (const float*)p_msg);

    // 6) y = cat @ W1^T + b   [16384,512]
    sgemm_kernel<false><<<dim3(512 / 64, Mq / 64), 256>>>(
        (const float*)p_cat, W1_w, W1_b, nullptr, (float*)p_y, Mq, 512, 512);

    // 7) LayerNorm + GELU (in place)
    ln_gelu_kernel<<<Mq, 256>>>(ln_g, ln_b);

    // 8) out = desc + y @ W2^T + b
    sgemm_kernel<true><<<dim3(Dq / 64, Mq / 64), 256>>>(
        (const float*)p_y, W2_w, W2_b, desc, out, Mq, Dq, 512);
}

// round 3
// speedup vs baseline: 1.3609x; 1.3609x over previous
#include <cuda_runtime.h>
#include <cuda_bf16.h>
#include <math.h>
#include <stdint.h>

// Problem constants
#define Bq   8
#define Sq   2048
#define Dq   256
#define Hq   4
#define Dh   64
#define Mq   (Bq * Sq)        // 16384 rows

// ---------------- scratch (device globals; no allocation allowed) ----------
__device__ float g_qkv[Mq * 3 * Dq];          // [16384, 768]
__device__ float g_q  [Bq * Hq * Sq * Dh];    // [B,H,S,Dh]
__device__ float g_k  [Bq * Hq * Sq * Dh];
__device__ float g_v  [Bq * Hq * Sq * Dh];
__device__ float g_ctx[Mq * Dq];              // [B,S,D]
__device__ float g_msg[Mq * Dq];
__device__ float g_cat[Mq * 2 * Dq];          // [16384, 512]
__device__ float g_y  [Mq * 2 * Dq];

// =====================  helpers ============================================
__device__ __forceinline__ uint32_t smem_u32(const void* p) {
    uint32_t a;
    asm("{ .reg .u64 t; cvta.to.shared.u64 t, %1; cvt.u32.u64 %0, t; }"
        : "=r"(a) : "l"(p));
    return a;
}
__device__ __forceinline__ void cp_async16(uint32_t saddr, const void* gaddr) {
    asm volatile("cp.async.cg.shared.global [%0], [%1], 16;\n"
                 :: "r"(saddr), "l"(gaddr));
}
#define CP_COMMIT() asm volatile("cp.async.commit_group;" ::: "memory")
#define CP_WAIT1()  asm volatile("cp.async.wait_group 1;" ::: "memory")

// m16n8k8 tf32 mma: D = A*B + D (fp32 accum). Raw fp32 bits as tf32.
__device__ __forceinline__ void mma_tf32(float* d, const uint32_t* a, const uint32_t* b) {
    asm volatile(
        "mma.sync.aligned.m16n8k8.row.col.f32.tf32.tf32.f32 "
        "{%0,%1,%2,%3}, {%4,%5,%6,%7}, {%8,%9}, {%0,%1,%2,%3};"
        : "+f"(d[0]), "+f"(d[1]), "+f"(d[2]), "+f"(d[3])
        : "r"(a[0]), "r"(a[1]), "r"(a[2]), "r"(a[3]),
          "r"(b[0]), "r"(b[1]));
}

// ================  mma.sync tf32 GEMM:  C = A[M,K] @ W[N,K]^T + bias (+res) =
// CTA tile 128x128, 8 warps (4m x 2n), warp tile 32x64.
// smem stage: A[128][36], W[128][36] (32 useful floats + 4 pad; 144B rows).
#define TS        36
#define STAGE_F   (128 * TS)          // floats per operand per stage
#define G_STAGE_B (2 * STAGE_F * 4)   // bytes per stage
#define G_STAGES  3
#define G_SMEM_TOT (G_STAGES * G_STAGE_B)

template <bool RES>
__global__ void __launch_bounds__(256)
mma_gemm_kernel(const float* __restrict__ A, const float* __restrict__ W,
                const float* __restrict__ bias, const float* __restrict__ resid,
                float* __restrict__ C, int M, int N, int K) {
    extern __shared__ __align__(16) float sm[];
    const uint32_t sb = smem_u32(sm);
    const int tid  = threadIdx.x;
    const int wid  = tid >> 5;
    const int lane = tid & 31;
    const int g    = lane >> 2;      // group id 0..7
    const int t4   = lane & 3;       // thread-in-group 0..3
    const int bm = blockIdx.y * 128;
    const int bn = blockIdx.x * 128;
    const int wm = (wid & 3) * 32;   // warp m offset in tile
    const int wn = (wid >> 2) * 64;  // warp n offset in tile
    const int NT = K >> 5;           // k-stages of 32

    float acc[2][8][4];
#pragma unroll
    for (int i = 0; i < 2; i++)
#pragma unroll
        for (int j = 0; j < 8; j++)
#pragma unroll
            for (int c = 0; c < 4; c++) acc[i][j][c] = 0.f;

    // ---- stage loader: 256 threads, 4 float4 each per operand --------------
    auto ldstage = [&](int u) {
        const int slot = u % G_STAGES;
        const int k0 = u << 5;
        const uint32_t sbase = sb + (uint32_t)slot * G_STAGE_B;
#pragma unroll
        for (int i = 0; i < 4; i++) {
            const int idx = tid + i * 256;
            const int row = idx >> 3;
            const int ch  = idx & 7;
            cp_async16(sbase + (uint32_t)(row * TS + ch * 4) * 4,
                       A + (size_t)(bm + row) * K + k0 + ch * 4);
        }
#pragma unroll
        for (int i = 0; i < 4; i++) {
            const int idx = tid + i * 256;
            const int row = idx >> 3;
            const int ch  = idx & 7;
            cp_async16(sbase + (uint32_t)(STAGE_F + row * TS + ch * 4) * 4,
                       W + (size_t)(bn + row) * K + k0 + ch * 4);
        }
    };

    ldstage(0); CP_COMMIT();
    ldstage(1); CP_COMMIT();

    for (int t = 0; t < NT; t++) {
        CP_WAIT1();
        __syncthreads();
        if (t + 2 < NT) ldstage(t + 2);
        CP_COMMIT();

        const float* sA = sm + (size_t)(t % G_STAGES) * 2 * STAGE_F;
        const float* sW = sA + STAGE_F;
#pragma unroll
        for (int kc = 0; kc < 4; kc++) {
            const int k0 = kc * 8;
            uint32_t af[2][4];
#pragma unroll
            for (int mt = 0; mt < 2; mt++) {
                const int r0 = wm + mt * 16;
                af[mt][0] = __float_as_uint(sA[(r0 + g)     * TS + k0 + t4]);
                af[mt][1] = __float_as_uint(sA[(r0 + g + 8) * TS + k0 + t4]);
                af[mt][2] = __float_as_uint(sA[(r0 + g)     * TS + k0 + t4 + 4]);
                af[mt][3] = __float_as_uint(sA[(r0 + g + 8) * TS + k0 + t4 + 4]);
            }
#pragma unroll
            for (int nt = 0; nt < 8; nt++) {
                const int cn = wn + nt * 8 + g;
                uint32_t bf[2];
                bf[0] = __float_as_uint(sW[cn * TS + k0 + t4]);
                bf[1] = __float_as_uint(sW[cn * TS + k0 + t4 + 4]);
#pragma unroll
                for (int mt = 0; mt < 2; mt++)
                    mma_tf32(acc[mt][nt], af[mt], bf);
            }
        }
        __syncthreads();
    }

    // ---- epilogue: direct float2 stores ------------------------------------
#pragma unroll
    for (int nt = 0; nt < 8; nt++) {
        const int col = bn + wn + nt * 8 + t4 * 2;
        const float2 bv = *(const float2*)&bias[col];
#pragma unroll
        for (int mt = 0; mt < 2; mt++) {
            const int r0 = bm + wm + mt * 16 + g;
            float2 v0 = make_float2(acc[mt][nt][0] + bv.x, acc[mt][nt][1] + bv.y);
            float2 v1 = make_float2(acc[mt][nt][2] + bv.x, acc[mt][nt][3] + bv.y);
            if (RES) {
                const float2 r0v = *(const float2*)&resid[(size_t)r0 * N + col];
                const float2 r1v = *(const float2*)&resid[(size_t)(r0 + 8) * N + col];
                v0.x += r0v.x; v0.y += r0v.y;
                v1.x += r1v.x; v1.y += r1v.y;
            }
            *(float2*)&C[(size_t)r0 * N + col]       = v0;
            *(float2*)&C[(size_t)(r0 + 8) * N + col] = v1;
        }
    }
}

// ---------------- RoPE + split qkv into Q,K,V [B,H,S,Dh] -------------------
__global__ void rope_split_kernel(const float* __restrict__ qkv,
                                  const float* __restrict__ kp) {
    int idx = blockIdx.x * blockDim.x + threadIdx.x;   // one thread per pair
    const int p = idx & 31;
    const int h = (idx >> 5) & 3;
    const int s = (idx >> 7) & 2047;
    const int b = idx >> 18;
    const int d0 = p * 2;

    const float* src = qkv + ((size_t)(b * Sq + s)) * 768 + h * 192 + d0 * 3;
    float q0 = src[0], k0 = src[1], v0 = src[2];
    float q1 = src[3], k1 = src[4], v1 = src[5];

    const size_t kpo = ((size_t)b * Sq + s) * Dh + d0;
    float c0 = kp[kpo],                 c1 = kp[kpo + 1];
    float s0 = kp[(size_t)Bq * Sq * Dh + kpo];
    float s1 = kp[(size_t)Bq * Sq * Dh + kpo + 1];

    const float scale = 0.125f;  // 64^-0.5, fold into Q
    float qo0 = (q0 * c0 - q1 * s0) * scale;
    float qo1 = (q1 * c1 + q0 * s1) * scale;
    float ko0 = k0 * c0 - k1 * s0;
    float ko1 = k1 * c1 + k0 * s1;

    const size_t o = (((size_t)b * Hq + h) * Sq + s) * Dh + d0;
    g_q[o] = qo0; g_q[o + 1] = qo1;
    g_k[o] = ko0; g_k[o + 1] = ko1;
    g_v[o] = v0;  g_v[o + 1] = v1;
}

// ---------------- flash attention: 64x64 tiles, online softmax -------------
__global__ void flash_attn_kernel(const float* __restrict__ Q,
                                  const float* __restrict__ K,
                                  const float* __restrict__ V,
                                  float* __restrict__ ctx) {
    __shared__ float Qs[64][64];   // [d][r]
    __shared__ float Ks[64][64];   // [d][c]  (aliased as Ps[j][r] later)
    __shared__ float Vs[64][64];   // [j][d]

    const int b = blockIdx.z, h = blockIdx.y, it = blockIdx.x;
    const int tid = threadIdx.x;
    const int tx = tid & 15;
    const int ty = tid >> 4;
    const size_t base = (((size_t)b * Hq + h) * Sq) * (size_t)Dh;

    {
        const int r = tid >> 2;
        const int db = (tid & 3) * 16;
        const float* qp = Q + base + (size_t)(it * 64 + r) * Dh + db;
#pragma unroll
        for (int u = 0; u < 4; u++) {
            float4 v = *(const float4*)(qp + u * 4);
            Qs[db + u * 4 + 0][r] = v.x;
            Qs[db + u * 4 + 1][r] = v.y;
            Qs[db + u * 4 + 2][r] = v.z;
            Qs[db + u * 4 + 3][r] = v.w;
        }
    }

    float m_i[4], l_i[4], acc[4][4];
#pragma unroll
    for (int i = 0; i < 4; i++) {
        m_i[i] = -INFINITY; l_i[i] = 0.f;
#pragma unroll
        for (int j = 0; j < 4; j++) acc[i][j] = 0.f;
    }

    for (int jt = 0; jt < Sq / 64; jt++) {
        __syncthreads();
        {
            const int r = tid >> 2;
            const int db = (tid & 3) * 16;
            const float* kp2 = K + base + (size_t)(jt * 64 + r) * Dh + db;
            const float* vp  = V + base + (size_t)(jt * 64 + r) * Dh + db;
#pragma unroll
            for (int u = 0; u < 4; u++) {
                float4 v = *(const float4*)(kp2 + u * 4);
                Ks[db + u * 4 + 0][r] = v.x;
                Ks[db + u * 4 + 1][r] = v.y;
                Ks[db + u * 4 + 2][r] = v.z;
                Ks[db + u * 4 + 3][r] = v.w;
                *(float4*)&Vs[r][db + u * 4] = *(const float4*)(vp + u * 4);
            }
        }
        __syncthreads();

        float s[4][4] = {};
#pragma unroll
        for (int kk = 0; kk < 64; kk++) {
            float4 a4 = *(const float4*)&Qs[kk][ty * 4];
            float4 b4 = *(const float4*)&Ks[kk][tx * 4];
            float a[4] = {a4.x, a4.y, a4.z, a4.w};
            float bb[4] = {b4.x, b4.y, b4.z, b4.w};
#pragma unroll
            for (int i = 0; i < 4; i++)
#pragma unroll
                for (int j = 0; j < 4; j++)
                    s[i][j] = fmaf(a[i], bb[j], s[i][j]);
        }

#pragma unroll
        for (int i = 0; i < 4; i++) {
            float tmax = s[i][0];
#pragma unroll
            for (int j = 1; j < 4; j++) tmax = fmaxf(tmax, s[i][j]);
#pragma unroll
            for (int msk = 8; msk >= 1; msk >>= 1)
                tmax = fmaxf(tmax, __shfl_xor_sync(0xffffffffu, tmax, msk));
            const float mn = fmaxf(m_i[i], tmax);
            const float factor = __expf(m_i[i] - mn);
            float rs = 0.f;
#pragma unroll
            for (int j = 0; j < 4; j++) {
                s[i][j] = __expf(s[i][j] - mn);
                rs += s[i][j];
            }
#pragma unroll
            for (int msk = 8; msk >= 1; msk >>= 1)
                rs += __shfl_xor_sync(0xffffffffu, rs, msk);
            l_i[i] = l_i[i] * factor + rs;
            m_i[i] = mn;
#pragma unroll
            for (int j = 0; j < 4; j++) acc[i][j] *= factor;
        }

        __syncthreads();
#pragma unroll
        for (int i = 0; i < 4; i++)
#pragma unroll
            for (int j = 0; j < 4; j++)
                Ks[tx * 4 + j][ty * 4 + i] = s[i][j];
        __syncthreads();

#pragma unroll
        for (int kk = 0; kk < 64; kk++) {
            float4 a4 = *(const float4*)&Ks[kk][ty * 4];
            float4 b4 = *(const float4*)&Vs[kk][tx * 4];
            float a[4] = {a4.x, a4.y, a4.z, a4.w};
            float bb[4] = {b4.x, b4.y, b4.z, b4.w};
#pragma unroll
            for (int i = 0; i < 4; i++)
#pragma unroll
                for (int j = 0; j < 4; j++)
                    acc[i][j] = fmaf(a[i], bb[j], acc[i][j]);
        }
    }

#pragma unroll
    for (int i = 0; i < 4; i++) {
        const float inv = 1.f / l_i[i];
        const int r = it * 64 + ty * 4 + i;
#pragma unroll
        for (int j = 0; j < 4; j++)
            ctx[((size_t)b * Sq + r) * Dq + h * Dh + tx * 4 + j] = acc[i][j] * inv;
    }
}

// ---------------- concat(desc, msg) -> cat [16384,512] ---------------------
__global__ void concat_kernel(const float* __restrict__ desc,
                              const float* __restrict__ msg) {
    int idx = blockIdx.x * blockDim.x + threadIdx.x;
    const int m = idx >> 7;
    const int c4 = idx & 127;
    float4 v;
    if (c4 < 64) v = ((const float4*)desc)[(size_t)m * 64 + c4];
    else         v = ((const float4*)msg)[(size_t)m * 64 + (c4 - 64)];
    ((float4*)g_cat)[idx] = v;
}

// ---------------- LayerNorm(512) + exact GELU, in place on g_y -------------
__global__ void ln_gelu_kernel(const float* __restrict__ gamma,
                               const float* __restrict__ beta) {
    __shared__ float2 sh[8];
    const int m = blockIdx.x;
    float* row = g_y + (size_t)m * 512;
    const int t = threadIdx.x;

    float a = row[t], b = row[t + 256];
    float2 v = make_float2(a + b, a * a + b * b);
#pragma unroll
    for (int msk = 16; msk >= 1; msk >>= 1) {
        v.x += __shfl_xor_sync(0xffffffffu, v.x, msk);
        v.y += __shfl_xor_sync(0xffffffffu, v.y, msk);
    }
    const int lane = t & 31, w = t >> 5;
    if (lane == 0) sh[w] = v;
    __syncthreads();
    if (w == 0) {
        v = (lane < 8) ? sh[lane] : make_float2(0.f, 0.f);
#pragma unroll
        for (int msk = 4; msk >= 1; msk >>= 1) {
            v.x += __shfl_xor_sync(0xffffffffu, v.x, msk);
            v.y += __shfl_xor_sync(0xffffffffu, v.y, msk);
        }
        if (lane == 0) sh[0] = v;
    }
    __syncthreads();
    const float mu = sh[0].x * (1.f / 512.f);
    const float var = sh[0].y * (1.f / 512.f) - mu * mu;
    const float inv = rsqrtf(var + 1e-5f);

#pragma unroll
    for (int u = 0; u < 2; u++) {
        const int c = t + u * 256;
        float x = (row[c] - mu) * inv * gamma[c] + beta[c];
        row[c] = 0.5f * x * (1.f + erff(x * 0.70710678118654752440f));
    }
}

// ---------------- launch ----------------------------------------------------
extern "C" void kernel_launch(void* const* d_in, const int* in_sizes, int n_in,
                              void* d_out, int out_size) {
    const float* desc   = (const float*)d_in[0];
    const float* kp     = (const float*)d_in[1];
    const float* Wqkv_w = (const float*)d_in[2];
    const float* Wqkv_b = (const float*)d_in[3];
    const float* Wo_w   = (const float*)d_in[4];
    const float* Wo_b   = (const float*)d_in[5];
    const float* W1_w   = (const float*)d_in[6];
    const float* W1_b   = (const float*)d_in[7];
    const float* ln_g   = (const float*)d_in[8];
    const float* ln_b   = (const float*)d_in[9];
    const float* W2_w   = (const float*)d_in[10];
    const float* W2_b   = (const float*)d_in[11];
    float* out = (float*)d_out;

    void *p_qkv, *p_q, *p_k, *p_v, *p_ctx, *p_msg, *p_cat, *p_y;
    cudaGetSymbolAddress(&p_qkv, g_qkv);
    cudaGetSymbolAddress(&p_q,   g_q);
    cudaGetSymbolAddress(&p_k,   g_k);
    cudaGetSymbolAddress(&p_v,   g_v);
    cudaGetSymbolAddress(&p_ctx, g_ctx);
    cudaGetSymbolAddress(&p_msg, g_msg);
    cudaGetSymbolAddress(&p_cat, g_cat);
    cudaGetSymbolAddress(&p_y,   g_y);

    cudaFuncSetAttribute(mma_gemm_kernel<false>,
                         cudaFuncAttributeMaxDynamicSharedMemorySize, G_SMEM_TOT);
    cudaFuncSetAttribute(mma_gemm_kernel<true>,
                         cudaFuncAttributeMaxDynamicSharedMemorySize, G_SMEM_TOT);

    // 1) QKV = desc @ Wqkv^T + b   [16384,768]
    mma_gemm_kernel<false><<<dim3(768 / 128, Mq / 128), 256, G_SMEM_TOT>>>(
        desc, Wqkv_w, Wqkv_b, nullptr, (float*)p_qkv, Mq, 768, Dq);

    // 2) RoPE + split into Q,K,V [B,H,S,Dh]
    rope_split_kernel<<<(Bq * Sq * Hq * 32) / 256, 256>>>((const float*)p_qkv, kp);

    // 3) flash attention -> ctx [B,S,D]
    flash_attn_kernel<<<dim3(Sq / 64, Hq, Bq), 256>>>(
        (const float*)p_q, (const float*)p_k, (const float*)p_v, (float*)p_ctx);

    // 4) message = ctx @ Wo^T + b
    mma_gemm_kernel<false><<<dim3(Dq / 128, Mq / 128), 256, G_SMEM_TOT>>>(
        (const float*)p_ctx, Wo_w, Wo_b, nullptr, (float*)p_msg, Mq, Dq, Dq);

    // 5) cat = [desc, msg]
    concat_kernel<<<(Mq * 512 / 4) / 256, 256>>>(desc, (const float*)p_msg);

    // 6) y = cat @ W1^T + b   [16384,512]
    mma_gemm_kernel<false><<<dim3(512 / 128, Mq / 128), 256, G_SMEM_TOT>>>(
        (const float*)p_cat, W1_w, W1_b, nullptr, (float*)p_y, Mq, 512, 512);

    // 7) LayerNorm + GELU (in place)
    ln_gelu_kernel<<<Mq, 256>>>(ln_g, ln_b);

    // 8) out = desc + y @ W2^T + b
    mma_gemm_kernel<true><<<dim3(Dq / 128, Mq / 128), 256, G_SMEM_TOT>>>(
        (const float*)p_y, W2_w, W2_b, desc, out, Mq, Dq, 512);
}

// round 6
// speedup vs baseline: 3.8895x; 2.8580x over previous
#include <cuda_runtime.h>
#include <cuda_bf16.h>
#include <math.h>
#include <stdint.h>

// Problem constants
#define Bq   8
#define Sq   2048
#define Dq   256
#define Hq   4
#define Dh   64
#define Mq   (Bq * Sq)        // 16384 rows

// ---------------- scratch (device globals; no allocation allowed) ----------
__device__ float g_qkv[Mq * 3 * Dq];          // [16384, 768]
__device__ float g_q  [Bq * Hq * Sq * Dh];    // [B,H,S,Dh]
__device__ float g_k  [Bq * Hq * Sq * Dh];
__device__ float g_v  [Bq * Hq * Sq * Dh];
__device__ float g_ctx[Mq * Dq];              // [B,S,D]
__device__ float g_msg[Mq * Dq];
__device__ float g_cat[Mq * 2 * Dq];          // [16384, 512]
__device__ float g_y  [Mq * 2 * Dq];

// =====================  helpers ============================================
__device__ __forceinline__ uint32_t smem_u32(const void* p) {
    uint32_t a;
    asm("{ .reg .u64 t; cvta.to.shared.u64 t, %1; cvt.u32.u64 %0, t; }"
        : "=r"(a) : "l"(p));
    return a;
}
__device__ __forceinline__ void cp_async16(uint32_t saddr, const void* gaddr) {
    asm volatile("cp.async.cg.shared.global [%0], [%1], 16;\n"
                 :: "r"(saddr), "l"(gaddr));
}
#define CP_COMMIT() asm volatile("cp.async.commit_group;" ::: "memory")
#define CP_WAIT0()  asm volatile("cp.async.wait_group 0;" ::: "memory")
#define CP_WAIT1()  asm volatile("cp.async.wait_group 1;" ::: "memory")

// m16n8k8 tf32 mma: D = A*B + D (fp32 accum). Raw fp32 bits as tf32.
__device__ __forceinline__ void mma_tf32(float* d, const uint32_t* a, const uint32_t* b) {
    asm volatile(
        "mma.sync.aligned.m16n8k8.row.col.f32.tf32.tf32.f32 "
        "{%0,%1,%2,%3}, {%4,%5,%6,%7}, {%8,%9}, {%0,%1,%2,%3};"
        : "+f"(d[0]), "+f"(d[1]), "+f"(d[2]), "+f"(d[3])
        : "r"(a[0]), "r"(a[1]), "r"(a[2]), "r"(a[3]),
          "r"(b[0]), "r"(b[1]));
}

// ================  mma.sync tf32 GEMM:  C = A[M,K] @ W[N,K]^T + bias (+res) =
// CTA tile 128x128, 8 warps (4m x 2n), warp tile 32x64.
#define TS        36
#define STAGE_F   (128 * TS)
#define G_STAGE_B (2 * STAGE_F * 4)
#define G_STAGES  3
#define G_SMEM_TOT (G_STAGES * G_STAGE_B)

template <bool RES>
__global__ void __launch_bounds__(256)
mma_gemm_kernel(const float* __restrict__ A, const float* __restrict__ W,
                const float* __restrict__ bias, const float* __restrict__ resid,
                float* __restrict__ C, int M, int N, int K) {
    extern __shared__ __align__(16) float sm[];
    const uint32_t sb = smem_u32(sm);
    const int tid  = threadIdx.x;
    const int wid  = tid >> 5;
    const int lane = tid & 31;
    const int g    = lane >> 2;
    const int t4   = lane & 3;
    const int bm = blockIdx.y * 128;
    const int bn = blockIdx.x * 128;
    const int wm = (wid & 3) * 32;
    const int wn = (wid >> 2) * 64;
    const int NT = K >> 5;

    float acc[2][8][4];
#pragma unroll
    for (int i = 0; i < 2; i++)
#pragma unroll
        for (int j = 0; j < 8; j++)
#pragma unroll
            for (int c = 0; c < 4; c++) acc[i][j][c] = 0.f;

    auto ldstage = [&](int u) {
        const int slot = u % G_STAGES;
        const int k0 = u << 5;
        const uint32_t sbase = sb + (uint32_t)slot * G_STAGE_B;
#pragma unroll
        for (int i = 0; i < 4; i++) {
            const int idx = tid + i * 256;
            const int row = idx >> 3;
            const int ch  = idx & 7;
            cp_async16(sbase + (uint32_t)(row * TS + ch * 4) * 4,
                       A + (size_t)(bm + row) * K + k0 + ch * 4);
        }
#pragma unroll
        for (int i = 0; i < 4; i++) {
            const int idx = tid + i * 256;
            const int row = idx >> 3;
            const int ch  = idx & 7;
            cp_async16(sbase + (uint32_t)(STAGE_F + row * TS + ch * 4) * 4,
                       W + (size_t)(bn + row) * K + k0 + ch * 4);
        }
    };

    ldstage(0); CP_COMMIT();
    ldstage(1); CP_COMMIT();

    for (int t = 0; t < NT; t++) {
        CP_WAIT1();
        __syncthreads();
        if (t + 2 < NT) ldstage(t + 2);
        CP_COMMIT();

        const float* sA = sm + (size_t)(t % G_STAGES) * 2 * STAGE_F;
        const float* sW = sA + STAGE_F;
#pragma unroll
        for (int kc = 0; kc < 4; kc++) {
            const int k0 = kc * 8;
            uint32_t af[2][4];
#pragma unroll
            for (int mt = 0; mt < 2; mt++) {
                const int r0 = wm + mt * 16;
                af[mt][0] = __float_as_uint(sA[(r0 + g)     * TS + k0 + t4]);
                af[mt][1] = __float_as_uint(sA[(r0 + g + 8) * TS + k0 + t4]);
                af[mt][2] = __float_as_uint(sA[(r0 + g)     * TS + k0 + t4 + 4]);
                af[mt][3] = __float_as_uint(sA[(r0 + g + 8) * TS + k0 + t4 + 4]);
            }
#pragma unroll
            for (int nt = 0; nt < 8; nt++) {
                const int cn = wn + nt * 8 + g;
                uint32_t bf[2];
                bf[0] = __float_as_uint(sW[cn * TS + k0 + t4]);
                bf[1] = __float_as_uint(sW[cn * TS + k0 + t4 + 4]);
#pragma unroll
                for (int mt = 0; mt < 2; mt++)
                    mma_tf32(acc[mt][nt], af[mt], bf);
            }
        }
        __syncthreads();
    }

#pragma unroll
    for (int nt = 0; nt < 8; nt++) {
        const int col = bn + wn + nt * 8 + t4 * 2;
        const float2 bv = *(const float2*)&bias[col];
#pragma unroll
        for (int mt = 0; mt < 2; mt++) {
            const int r0 = bm + wm + mt * 16 + g;
            float2 v0 = make_float2(acc[mt][nt][0] + bv.x, acc[mt][nt][1] + bv.y);
            float2 v1 = make_float2(acc[mt][nt][2] + bv.x, acc[mt][nt][3] + bv.y);
            if (RES) {
                const float2 r0v = *(const float2*)&resid[(size_t)r0 * N + col];
                const float2 r1v = *(const float2*)&resid[(size_t)(r0 + 8) * N + col];
                v0.x += r0v.x; v0.y += r0v.y;
                v1.x += r1v.x; v1.y += r1v.y;
            }
            *(float2*)&C[(size_t)r0 * N + col]       = v0;
            *(float2*)&C[(size_t)(r0 + 8) * N + col] = v1;
        }
    }
}

// ---------------- RoPE + split qkv into Q,K,V [B,H,S,Dh] -------------------
__global__ void rope_split_kernel(const float* __restrict__ qkv,
                                  const float* __restrict__ kp) {
    int idx = blockIdx.x * blockDim.x + threadIdx.x;
    const int p = idx & 31;
    const int h = (idx >> 5) & 3;
    const int s = (idx >> 7) & 2047;
    const int b = idx >> 18;
    const int d0 = p * 2;

    const float* src = qkv + ((size_t)(b * Sq + s)) * 768 + h * 192 + d0 * 3;
    float q0 = src[0], k0 = src[1], v0 = src[2];
    float q1 = src[3], k1 = src[4], v1 = src[5];

    const size_t kpo = ((size_t)b * Sq + s) * Dh + d0;
    float c0 = kp[kpo],                 c1 = kp[kpo + 1];
    float s0 = kp[(size_t)Bq * Sq * Dh + kpo];
    float s1 = kp[(size_t)Bq * Sq * Dh + kpo + 1];

    const float scale = 0.125f;  // 64^-0.5, fold into Q
    float qo0 = (q0 * c0 - q1 * s0) * scale;
    float qo1 = (q1 * c1 + q0 * s1) * scale;
    float ko0 = k0 * c0 - k1 * s0;
    float ko1 = k1 * c1 + k0 * s1;

    const size_t o = (((size_t)b * Hq + h) * Sq + s) * Dh + d0;
    g_q[o] = qo0; g_q[o + 1] = qo1;
    g_k[o] = ko0; g_k[o + 1] = ko1;
    g_v[o] = v0;  g_v[o + 1] = v1;
}

// ============== flash attention with m16n8k8 tf32 mma ======================
// Grid (S/128, H, B), 256 threads (8 warps). Warp w owns q-rows w*16..w*16+15.
// K/V tiles 64x64, double-buffered cp.async. Q prescaled by Dh^-0.5.
#define ATT_KPAD 68
#define ATT_VPAD 72
#define ATT_KSTG (64 * ATT_KPAD)
#define ATT_VSTG (64 * ATT_VPAD)
#define ATT_SMEM ((2 * ATT_KSTG + 2 * ATT_VSTG) * 4)

__global__ void __launch_bounds__(256)
fa_mma_kernel(const float* __restrict__ Q, const float* __restrict__ K,
              const float* __restrict__ V, float* __restrict__ ctx) {
    extern __shared__ __align__(16) float sm[];
    float* Ks = sm;                        // 2 stages [64][68] (Q staging too)
    float* Vs = sm + 2 * ATT_KSTG;         // 2 stages [64][72]
    const uint32_t sKu = smem_u32(Ks);
    const uint32_t sVu = smem_u32(Vs);

    const int tid = threadIdx.x, wid = tid >> 5, lane = tid & 31;
    const int g = lane >> 2, t4 = lane & 3;
    const int b = blockIdx.z, h = blockIdx.y, it = blockIdx.x;
    const size_t base = ((size_t)(b * Hq + h)) * Sq * Dh;

    // ---- stage Q tile (128x64) into K region, pad 68 ----------------------
    {
        const float* Qg = Q + base + (size_t)it * 128 * Dh;
#pragma unroll
        for (int i = 0; i < 8; i++) {
            const int idx = tid + i * 256;       // 2048 chunks
            const int row = idx >> 4;
            const int ch  = idx & 15;
            cp_async16(sKu + (uint32_t)(row * ATT_KPAD + ch * 4) * 4,
                       Qg + row * 64 + ch * 4);
        }
    }
    CP_COMMIT(); CP_WAIT0();
    __syncthreads();

    // Q A-frags: rows wid*16+{g,g+8}, 8 k-blocks
    uint32_t aq[8][4];
    {
        const int qr = wid * 16;
#pragma unroll
        for (int kb = 0; kb < 8; kb++) {
            aq[kb][0] = __float_as_uint(Ks[(qr + g)     * ATT_KPAD + kb * 8 + t4]);
            aq[kb][1] = __float_as_uint(Ks[(qr + g + 8) * ATT_KPAD + kb * 8 + t4]);
            aq[kb][2] = __float_as_uint(Ks[(qr + g)     * ATT_KPAD + kb * 8 + t4 + 4]);
            aq[kb][3] = __float_as_uint(Ks[(qr + g + 8) * ATT_KPAD + kb * 8 + t4 + 4]);
        }
    }
    __syncthreads();   // done reading Q; K stage 0 may overwrite

    const float* Kg = K + base;
    const float* Vg = V + base;
    auto ldkv = [&](int jt) {
        const int slot = jt & 1;
#pragma unroll
        for (int i = 0; i < 4; i++) {
            const int idx = tid + i * 256;       // 1024 chunks each
            const int row = idx >> 4;
            const int ch  = idx & 15;
            cp_async16(sKu + (uint32_t)(slot * ATT_KSTG + row * ATT_KPAD + ch * 4) * 4,
                       Kg + (size_t)(jt * 64 + row) * 64 + ch * 4);
            cp_async16(sVu + (uint32_t)(slot * ATT_VSTG + row * ATT_VPAD + ch * 4) * 4,
                       Vg + (size_t)(jt * 64 + row) * 64 + ch * 4);
        }
    };

    ldkv(0); CP_COMMIT();

    float m0 = -INFINITY, m1 = -INFINITY, l0 = 0.f, l1 = 0.f;
    float o[8][4];
#pragma unroll
    for (int nt = 0; nt < 8; nt++)
#pragma unroll
        for (int c = 0; c < 4; c++) o[nt][c] = 0.f;

    for (int jt = 0; jt < Sq / 64; jt++) {
        if (jt + 1 < Sq / 64) { ldkv(jt + 1); CP_COMMIT(); CP_WAIT1(); }
        else                  { CP_WAIT0(); }
        __syncthreads();

        const float* Kt = Ks + (jt & 1) * ATT_KSTG;
        const float* Vt = Vs + (jt & 1) * ATT_VSTG;

        // ---- S = Q K^T  (tile 16x64 per warp) -----------------------------
        float sc[8][4];
#pragma unroll
        for (int nt = 0; nt < 8; nt++) {
#pragma unroll
            for (int c = 0; c < 4; c++) sc[nt][c] = 0.f;
            const float* kr = Kt + (nt * 8 + g) * ATT_KPAD;
#pragma unroll
            for (int kb = 0; kb < 8; kb++) {
                uint32_t bf[2];
                bf[0] = __float_as_uint(kr[kb * 8 + t4]);
                bf[1] = __float_as_uint(kr[kb * 8 + t4 + 4]);
                mma_tf32(sc[nt], aq[kb], bf);
            }
        }

        // ---- online softmax (rows g, g+8 of this warp's 16) ---------------
        float mx0 = -INFINITY, mx1 = -INFINITY;
#pragma unroll
        for (int nt = 0; nt < 8; nt++) {
            mx0 = fmaxf(mx0, fmaxf(sc[nt][0], sc[nt][1]));
            mx1 = fmaxf(mx1, fmaxf(sc[nt][2], sc[nt][3]));
        }
        mx0 = fmaxf(mx0, __shfl_xor_sync(0xffffffffu, mx0, 1));
        mx0 = fmaxf(mx0, __shfl_xor_sync(0xffffffffu, mx0, 2));
        mx1 = fmaxf(mx1, __shfl_xor_sync(0xffffffffu, mx1, 1));
        mx1 = fmaxf(mx1, __shfl_xor_sync(0xffffffffu, mx1, 2));

        const float nm0 = fmaxf(m0, mx0);
        const float nm1 = fmaxf(m1, mx1);
        const float f0 = __expf(m0 - nm0);
        const float f1 = __expf(m1 - nm1);
        float sum0 = 0.f, sum1 = 0.f;
#pragma unroll
        for (int nt = 0; nt < 8; nt++) {
            sc[nt][0] = __expf(sc[nt][0] - nm0);
            sc[nt][1] = __expf(sc[nt][1] - nm0);
            sc[nt][2] = __expf(sc[nt][2] - nm1);
            sc[nt][3] = __expf(sc[nt][3] - nm1);
            sum0 += sc[nt][0] + sc[nt][1];
            sum1 += sc[nt][2] + sc[nt][3];
        }
        sum0 += __shfl_xor_sync(0xffffffffu, sum0, 1);
        sum0 += __shfl_xor_sync(0xffffffffu, sum0, 2);
        sum1 += __shfl_xor_sync(0xffffffffu, sum1, 1);
        sum1 += __shfl_xor_sync(0xffffffffu, sum1, 2);
        l0 = l0 * f0 + sum0;
        l1 = l1 * f1 + sum1;
        m0 = nm0; m1 = nm1;
#pragma unroll
        for (int nt = 0; nt < 8; nt++) {
            o[nt][0] *= f0; o[nt][1] *= f0;
            o[nt][2] *= f1; o[nt][3] *= f1;
        }

        // ---- O += P V  (P C-frags -> A-frags via intra-quad shuffles) -----
        const int qbase = lane & ~3;
        const int src0 = qbase + (t4 >> 1);
        const int src1 = src0 + 2;
        const bool odd = (t4 & 1);
#pragma unroll
        for (int kb = 0; kb < 8; kb++) {
            float s00 = __shfl_sync(0xffffffffu, sc[kb][0], src0);
            float s01 = __shfl_sync(0xffffffffu, sc[kb][1], src0);
            float s02 = __shfl_sync(0xffffffffu, sc[kb][2], src0);
            float s03 = __shfl_sync(0xffffffffu, sc[kb][3], src0);
            float s10 = __shfl_sync(0xffffffffu, sc[kb][0], src1);
            float s11 = __shfl_sync(0xffffffffu, sc[kb][1], src1);
            float s12 = __shfl_sync(0xffffffffu, sc[kb][2], src1);
            float s13 = __shfl_sync(0xffffffffu, sc[kb][3], src1);
            uint32_t ap[4];
            ap[0] = __float_as_uint(odd ? s01 : s00);   // row g,   col t4
            ap[1] = __float_as_uint(odd ? s03 : s02);   // row g+8, col t4
            ap[2] = __float_as_uint(odd ? s11 : s10);   // row g,   col t4+4
            ap[3] = __float_as_uint(odd ? s13 : s12);   // row g+8, col t4+4
            const float* vr0 = Vt + (kb * 8 + t4) * ATT_VPAD;
            const float* vr1 = Vt + (kb * 8 + t4 + 4) * ATT_VPAD;
#pragma unroll
            for (int nt = 0; nt < 8; nt++) {
                uint32_t bf[2];
                bf[0] = __float_as_uint(vr0[nt * 8 + g]);
                bf[1] = __float_as_uint(vr1[nt * 8 + g]);
                mma_tf32(o[nt], ap, bf);
            }
        }
        __syncthreads();   // compute done before next ldkv overwrites
    }

    // ---- normalize + write ctx[b, row, h*64+d] -----------------------------
    const float il0 = 1.f / l0;
    const float il1 = 1.f / l1;
    const int row0 = it * 128 + wid * 16 + g;
#pragma unroll
    for (int nt = 0; nt < 8; nt++) {
        const int col = h * Dh + nt * 8 + t4 * 2;
        float2 v0 = make_float2(o[nt][0] * il0, o[nt][1] * il0);
        float2 v1 = make_float2(o[nt][2] * il1, o[nt][3] * il1);
        *(float2*)&ctx[((size_t)b * Sq + row0) * Dq + col]     = v0;
        *(float2*)&ctx[((size_t)b * Sq + row0 + 8) * Dq + col] = v1;
    }
}

// ---------------- concat(desc, msg) -> cat [16384,512] ---------------------
__global__ void concat_kernel(const float* __restrict__ desc,
                              const float* __restrict__ msg) {
    int idx = blockIdx.x * blockDim.x + threadIdx.x;
    const int m = idx >> 7;
    const int c4 = idx & 127;
    float4 v;
    if (c4 < 64) v = ((const float4*)desc)[(size_t)m * 64 + c4];
    else         v = ((const float4*)msg)[(size_t)m * 64 + (c4 - 64)];
    ((float4*)g_cat)[idx] = v;
}

// ---------------- LayerNorm(512) + exact GELU, in place on g_y -------------
__global__ void ln_gelu_kernel(const float* __restrict__ gamma,
                               const float* __restrict__ beta) {
    __shared__ float2 sh[8];
    const int m = blockIdx.x;
    float* row = g_y + (size_t)m * 512;
    const int t = threadIdx.x;

    float a = row[t], b = row[t + 256];
    float2 v = make_float2(a + b, a * a + b * b);
#pragma unroll
    for (int msk = 16; msk >= 1; msk >>= 1) {
        v.x += __shfl_xor_sync(0xffffffffu, v.x, msk);
        v.y += __shfl_xor_sync(0xffffffffu, v.y, msk);
    }
    const int lane = t & 31, w = t >> 5;
    if (lane == 0) sh[w] = v;
    __syncthreads();
    if (w == 0) {
        v = (lane < 8) ? sh[lane] : make_float2(0.f, 0.f);
#pragma unroll
        for (int msk = 4; msk >= 1; msk >>= 1) {
            v.x += __shfl_xor_sync(0xffffffffu, v.x, msk);
            v.y += __shfl_xor_sync(0xffffffffu, v.y, msk);
        }
        if (lane == 0) sh[0] = v;
    }
    __syncthreads();
    const float mu = sh[0].x * (1.f / 512.f);
    const float var = sh[0].y * (1.f / 512.f) - mu * mu;
    const float inv = rsqrtf(var + 1e-5f);

#pragma unroll
    for (int u = 0; u < 2; u++) {
        const int c = t + u * 256;
        float x = (row[c] - mu) * inv * gamma[c] + beta[c];
        row[c] = 0.5f * x * (1.f + erff(x * 0.70710678118654752440f));
    }
}

// ---------------- launch ----------------------------------------------------
extern "C" void kernel_launch(void* const* d_in, const int* in_sizes, int n_in,
                              void* d_out, int out_size) {
    const float* desc   = (const float*)d_in[0];
    const float* kp     = (const float*)d_in[1];
    const float* Wqkv_w = (const float*)d_in[2];
    const float* Wqkv_b = (const float*)d_in[3];
    const float* Wo_w   = (const float*)d_in[4];
    const float* Wo_b   = (const float*)d_in[5];
    const float* W1_w   = (const float*)d_in[6];
    const float* W1_b   = (const float*)d_in[7];
    const float* ln_g   = (const float*)d_in[8];
    const float* ln_b   = (const float*)d_in[9];
    const float* W2_w   = (const float*)d_in[10];
    const float* W2_b   = (const float*)d_in[11];
    float* out = (float*)d_out;

    void *p_qkv, *p_q, *p_k, *p_v, *p_ctx, *p_msg, *p_cat, *p_y;
    cudaGetSymbolAddress(&p_qkv, g_qkv);
    cudaGetSymbolAddress(&p_q,   g_q);
    cudaGetSymbolAddress(&p_k,   g_k);
    cudaGetSymbolAddress(&p_v,   g_v);
    cudaGetSymbolAddress(&p_ctx, g_ctx);
    cudaGetSymbolAddress(&p_msg, g_msg);
    cudaGetSymbolAddress(&p_cat, g_cat);
    cudaGetSymbolAddress(&p_y,   g_y);

    cudaFuncSetAttribute(mma_gemm_kernel<false>,
                         cudaFuncAttributeMaxDynamicSharedMemorySize, G_SMEM_TOT);
    cudaFuncSetAttribute(mma_gemm_kernel<true>,
                         cudaFuncAttributeMaxDynamicSharedMemorySize, G_SMEM_TOT);
    cudaFuncSetAttribute(fa_mma_kernel,
                         cudaFuncAttributeMaxDynamicSharedMemorySize, ATT_SMEM);

    // 1) QKV = desc @ Wqkv^T + b   [16384,768]
    mma_gemm_kernel<false><<<dim3(768 / 128, Mq / 128), 256, G_SMEM_TOT>>>(
        desc, Wqkv_w, Wqkv_b, nullptr, (float*)p_qkv, Mq, 768, Dq);

    // 2) RoPE + split into Q,K,V [B,H,S,Dh]
    rope_split_kernel<<<(Bq * Sq * Hq * 32) / 256, 256>>>((const float*)p_qkv, kp);

    // 3) flash attention (tensor-core) -> ctx [B,S,D]
    fa_mma_kernel<<<dim3(Sq / 128, Hq, Bq), 256, ATT_SMEM>>>(
        (const float*)p_q, (const float*)p_k, (const float*)p_v, (float*)p_ctx);

    // 4) message = ctx @ Wo^T + b
    mma_gemm_kernel<false><<<dim3(Dq / 128, Mq / 128), 256, G_SMEM_TOT>>>(
        (const float*)p_ctx, Wo_w, Wo_b, nullptr, (float*)p_msg, Mq, Dq, Dq);

    // 5) cat = [desc, msg]
    concat_kernel<<<(Mq * 512 / 4) / 256, 256>>>(desc, (const float*)p_msg);

    // 6) y = cat @ W1^T + b   [16384,512]
    mma_gemm_kernel<false><<<dim3(512 / 128, Mq / 128), 256, G_SMEM_TOT>>>(
        (const float*)p_cat, W1_w, W1_b, nullptr, (float*)p_y, Mq, 512, 512);

    // 7) LayerNorm + GELU (in place)
    ln_gelu_kernel<<<Mq, 256>>>(ln_g, ln_b);

    // 8) out = desc + y @ W2^T + b
    mma_gemm_kernel<true><<<dim3(Dq / 128, Mq / 128), 256, G_SMEM_TOT>>>(
        (const float*)p_y, W2_w, W2_b, desc, out, Mq, Dq, 512);
}

// round 7
// speedup vs baseline: 4.0919x; 1.0521x over previous
#include <cuda_runtime.h>
#include <cuda_bf16.h>
#include <math.h>
#include <stdint.h>

// Problem constants
#define Bq   8
#define Sq   2048
#define Dq   256
#define Hq   4
#define Dh   64
#define Mq   (Bq * Sq)        // 16384 rows

// ---------------- scratch (device globals; no allocation allowed) ----------
__device__ float g_q  [Bq * Hq * Sq * Dh];    // [B,H,S,Dh]
__device__ float g_k  [Bq * Hq * Sq * Dh];
__device__ float g_v  [Bq * Hq * Sq * Dh];
__device__ float g_ctx[Mq * Dq];              // [B,S,D]
__device__ float g_msg[Mq * Dq];
__device__ float g_y  [Mq * 2 * Dq];

// =====================  helpers ============================================
__device__ __forceinline__ uint32_t smem_u32(const void* p) {
    uint32_t a;
    asm("{ .reg .u64 t; cvta.to.shared.u64 t, %1; cvt.u32.u64 %0, t; }"
        : "=r"(a) : "l"(p));
    return a;
}
__device__ __forceinline__ void cp_async16(uint32_t saddr, const void* gaddr) {
    asm volatile("cp.async.cg.shared.global [%0], [%1], 16;\n"
                 :: "r"(saddr), "l"(gaddr));
}
#define CP_COMMIT() asm volatile("cp.async.commit_group;" ::: "memory")
#define CP_WAIT0()  asm volatile("cp.async.wait_group 0;" ::: "memory")
#define CP_WAIT1()  asm volatile("cp.async.wait_group 1;" ::: "memory")

// m16n8k8 tf32 mma: D = A*B + D (fp32 accum). Raw fp32 bits as tf32.
__device__ __forceinline__ void mma_tf32(float* d, const uint32_t* a, const uint32_t* b) {
    asm volatile(
        "mma.sync.aligned.m16n8k8.row.col.f32.tf32.tf32.f32 "
        "{%0,%1,%2,%3}, {%4,%5,%6,%7}, {%8,%9}, {%0,%1,%2,%3};"
        : "+f"(d[0]), "+f"(d[1]), "+f"(d[2]), "+f"(d[3])
        : "r"(a[0]), "r"(a[1]), "r"(a[2]), "r"(a[3]),
          "r"(b[0]), "r"(b[1]));
}

// ================  shared GEMM tile config =================================
// CTA tile 128x128, 8 warps (4m x 2n), warp tile 32x64, 2-stage cp.async.
#define TS        36
#define STAGE_F   (128 * TS)
#define G_STAGE_B (2 * STAGE_F * 4)
#define G_STAGES  2
#define G_SMEM_TOT (G_STAGES * G_STAGE_B)

// ================  generic GEMM: C = A[M,K] @ W[N,K]^T + bias (+res) =======
// If A2 != null, A covers k<256 and A2 covers k>=256 (both row-stride 256).
template <bool RES>
__global__ void __launch_bounds__(256)
mma_gemm_kernel(const float* __restrict__ A, const float* __restrict__ A2,
                const float* __restrict__ W,
                const float* __restrict__ bias, const float* __restrict__ resid,
                float* __restrict__ C, int M, int N, int K, int lda) {
    extern __shared__ __align__(16) float sm[];
    const uint32_t sb = smem_u32(sm);
    const int tid  = threadIdx.x;
    const int wid  = tid >> 5;
    const int lane = tid & 31;
    const int g    = lane >> 2;
    const int t4   = lane & 3;
    const int bm = blockIdx.y * 128;
    const int bn = blockIdx.x * 128;
    const int wm = (wid & 3) * 32;
    const int wn = (wid >> 2) * 64;
    const int NT = K >> 5;

    float acc[2][8][4];
#pragma unroll
    for (int i = 0; i < 2; i++)
#pragma unroll
        for (int j = 0; j < 8; j++)
#pragma unroll
            for (int c = 0; c < 4; c++) acc[i][j][c] = 0.f;

    auto ldstage = [&](int u) {
        const int slot = u & 1;
        const int k0 = u << 5;
        const float* srcA = A;
        int ka = k0;
        if (A2 != nullptr && k0 >= 256) { srcA = A2; ka = k0 - 256; }
        const uint32_t sbase = sb + (uint32_t)slot * G_STAGE_B;
#pragma unroll
        for (int i = 0; i < 4; i++) {
            const int idx = tid + i * 256;
            const int row = idx >> 3;
            const int ch  = idx & 7;
            cp_async16(sbase + (uint32_t)(row * TS + ch * 4) * 4,
                       srcA + (size_t)(bm + row) * lda + ka + ch * 4);
        }
#pragma unroll
        for (int i = 0; i < 4; i++) {
            const int idx = tid + i * 256;
            const int row = idx >> 3;
            const int ch  = idx & 7;
            cp_async16(sbase + (uint32_t)(STAGE_F + row * TS + ch * 4) * 4,
                       W + (size_t)(bn + row) * K + k0 + ch * 4);
        }
    };

    ldstage(0); CP_COMMIT();
    ldstage(1); CP_COMMIT();

    for (int t = 0; t < NT; t++) {
        CP_WAIT1();
        __syncthreads();

        const float* sA = sm + (size_t)(t & 1) * 2 * STAGE_F;
        const float* sW = sA + STAGE_F;
#pragma unroll
        for (int kc = 0; kc < 4; kc++) {
            const int k0 = kc * 8;
            uint32_t af[2][4];
#pragma unroll
            for (int mt = 0; mt < 2; mt++) {
                const int r0 = wm + mt * 16;
                af[mt][0] = __float_as_uint(sA[(r0 + g)     * TS + k0 + t4]);
                af[mt][1] = __float_as_uint(sA[(r0 + g + 8) * TS + k0 + t4]);
                af[mt][2] = __float_as_uint(sA[(r0 + g)     * TS + k0 + t4 + 4]);
                af[mt][3] = __float_as_uint(sA[(r0 + g + 8) * TS + k0 + t4 + 4]);
            }
#pragma unroll
            for (int nt = 0; nt < 8; nt++) {
                const int cn = wn + nt * 8 + g;
                uint32_t bf[2];
                bf[0] = __float_as_uint(sW[cn * TS + k0 + t4]);
                bf[1] = __float_as_uint(sW[cn * TS + k0 + t4 + 4]);
#pragma unroll
                for (int mt = 0; mt < 2; mt++)
                    mma_tf32(acc[mt][nt], af[mt], bf);
            }
        }
        __syncthreads();
        if (t + 2 < NT) ldstage(t + 2);
        CP_COMMIT();
    }

#pragma unroll
    for (int nt = 0; nt < 8; nt++) {
        const int col = bn + wn + nt * 8 + t4 * 2;
        const float2 bv = *(const float2*)&bias[col];
#pragma unroll
        for (int mt = 0; mt < 2; mt++) {
            const int r0 = bm + wm + mt * 16 + g;
            float2 v0 = make_float2(acc[mt][nt][0] + bv.x, acc[mt][nt][1] + bv.y);
            float2 v1 = make_float2(acc[mt][nt][2] + bv.x, acc[mt][nt][3] + bv.y);
            if (RES) {
                const float2 r0v = *(const float2*)&resid[(size_t)r0 * N + col];
                const float2 r1v = *(const float2*)&resid[(size_t)(r0 + 8) * N + col];
                v0.x += r0v.x; v0.y += r0v.y;
                v1.x += r1v.x; v1.y += r1v.y;
            }
            *(float2*)&C[(size_t)r0 * N + col]       = v0;
            *(float2*)&C[(size_t)(r0 + 8) * N + col] = v1;
        }
    }
}

// ================  QKV GEMM + fused RoPE + split ===========================
// Canonical output col n' in [0,768): t=n'>>8 (0=q,1=k,2=v), h=(n'>>6)&3,
// d=n'&63. W rows permuted at load: src = h*192 + d*3 + t.
// Epilogue applies RoPE to q/k (q prescaled by Dh^-0.5) and writes [B,H,S,Dh].
__global__ void __launch_bounds__(256)
qkv_gemm_rope_kernel(const float* __restrict__ A, const float* __restrict__ W,
                     const float* __restrict__ bias, const float* __restrict__ kp) {
    extern __shared__ __align__(16) float sm[];
    const uint32_t sb = smem_u32(sm);
    const int tid  = threadIdx.x;
    const int wid  = tid >> 5;
    const int lane = tid & 31;
    const int g    = lane >> 2;
    const int t4   = lane & 3;
    const int bm = blockIdx.y * 128;
    const int bn = blockIdx.x * 128;
    const int wm = (wid & 3) * 32;
    const int wn = (wid >> 2) * 64;
    const int NT = 8;                       // K = 256

    float acc[2][8][4];
#pragma unroll
    for (int i = 0; i < 2; i++)
#pragma unroll
        for (int j = 0; j < 8; j++)
#pragma unroll
            for (int c = 0; c < 4; c++) acc[i][j][c] = 0.f;

    auto ldstage = [&](int u) {
        const int slot = u & 1;
        const int k0 = u << 5;
        const uint32_t sbase = sb + (uint32_t)slot * G_STAGE_B;
#pragma unroll
        for (int i = 0; i < 4; i++) {
            const int idx = tid + i * 256;
            const int row = idx >> 3;
            const int ch  = idx & 7;
            cp_async16(sbase + (uint32_t)(row * TS + ch * 4) * 4,
                       A + (size_t)(bm + row) * 256 + k0 + ch * 4);
        }
#pragma unroll
        for (int i = 0; i < 4; i++) {
            const int idx = tid + i * 256;
            const int row = idx >> 3;
            const int ch  = idx & 7;
            const int rp  = bn + row;              // canonical col
            const int tt  = rp >> 8;
            const int hh  = (rp >> 6) & 3;
            const int dd  = rp & 63;
            const int src = hh * 192 + dd * 3 + tt;
            cp_async16(sbase + (uint32_t)(STAGE_F + row * TS + ch * 4) * 4,
                       W + (size_t)src * 256 + k0 + ch * 4);
        }
    };

    ldstage(0); CP_COMMIT();
    ldstage(1); CP_COMMIT();

    for (int t = 0; t < NT; t++) {
        CP_WAIT1();
        __syncthreads();

        const float* sA = sm + (size_t)(t & 1) * 2 * STAGE_F;
        const float* sW = sA + STAGE_F;
#pragma unroll
        for (int kc = 0; kc < 4; kc++) {
            const int k0 = kc * 8;
            uint32_t af[2][4];
#pragma unroll
            for (int mt = 0; mt < 2; mt++) {
                const int r0 = wm + mt * 16;
                af[mt][0] = __float_as_uint(sA[(r0 + g)     * TS + k0 + t4]);
                af[mt][1] = __float_as_uint(sA[(r0 + g + 8) * TS + k0 + t4]);
                af[mt][2] = __float_as_uint(sA[(r0 + g)     * TS + k0 + t4 + 4]);
                af[mt][3] = __float_as_uint(sA[(r0 + g + 8) * TS + k0 + t4 + 4]);
            }
#pragma unroll
            for (int nt = 0; nt < 8; nt++) {
                const int cn = wn + nt * 8 + g;
                uint32_t bf[2];
                bf[0] = __float_as_uint(sW[cn * TS + k0 + t4]);
                bf[1] = __float_as_uint(sW[cn * TS + k0 + t4 + 4]);
#pragma unroll
                for (int mt = 0; mt < 2; mt++)
                    mma_tf32(acc[mt][nt], af[mt], bf);
            }
        }
        __syncthreads();
        if (t + 2 < NT) ldstage(t + 2);
        CP_COMMIT();
    }

    // ---- epilogue: bias + RoPE + scatter to g_q/g_k/g_v --------------------
    const int type = bn >> 8;               // 0=q, 1=k, 2=v (uniform per CTA)
    float* dst = (type == 0) ? g_q : (type == 1) ? g_k : g_v;
    const float qs = (type == 0) ? 0.125f : 1.0f;

#pragma unroll
    for (int nt = 0; nt < 8; nt++) {
        const int colp = bn + wn + nt * 8 + t4 * 2;   // canonical col (even)
        const int h = (colp >> 6) & 3;
        const int d = colp & 63;
        const float b0 = bias[h * 192 + d * 3 + type];
        const float b1 = bias[h * 192 + (d + 1) * 3 + type];
#pragma unroll
        for (int mt = 0; mt < 2; mt++) {
            const int mA = bm + wm + mt * 16 + g;
#pragma unroll
            for (int rr = 0; rr < 2; rr++) {
                const int m = mA + rr * 8;
                float x0 = acc[mt][nt][rr * 2 + 0] + b0;
                float x1 = acc[mt][nt][rr * 2 + 1] + b1;
                float o0 = x0, o1 = x1;
                if (type < 2) {
                    const float2 c2 = *(const float2*)&kp[(size_t)m * 64 + d];
                    const float2 s2 = *(const float2*)&kp[(size_t)Mq * 64 + (size_t)m * 64 + d];
                    o0 = (x0 * c2.x - x1 * s2.x) * qs;
                    o1 = (x1 * c2.y + x0 * s2.y) * qs;
                }
                const int bb = m >> 11;
                const int ss = m & 2047;
                const size_t off = (((size_t)(bb * 4 + h)) * 2048 + ss) * 64 + d;
                *(float2*)&dst[off] = make_float2(o0, o1);
            }
        }
    }
}

// ============== flash attention with m16n8k8 tf32 mma ======================
#define ATT_KPAD 68
#define ATT_VPAD 72
#define ATT_KSTG (64 * ATT_KPAD)
#define ATT_VSTG (64 * ATT_VPAD)
#define ATT_SMEM ((2 * ATT_KSTG + 2 * ATT_VSTG) * 4)

__global__ void __launch_bounds__(256)
fa_mma_kernel(const float* __restrict__ Q, const float* __restrict__ K,
              const float* __restrict__ V, float* __restrict__ ctx) {
    extern __shared__ __align__(16) float sm[];
    float* Ks = sm;
    float* Vs = sm + 2 * ATT_KSTG;
    const uint32_t sKu = smem_u32(Ks);
    const uint32_t sVu = smem_u32(Vs);

    const int tid = threadIdx.x, wid = tid >> 5, lane = tid & 31;
    const int g = lane >> 2, t4 = lane & 3;
    const int b = blockIdx.z, h = blockIdx.y, it = blockIdx.x;
    const size_t base = ((size_t)(b * Hq + h)) * Sq * Dh;

    {
        const float* Qg = Q + base + (size_t)it * 128 * Dh;
#pragma unroll
        for (int i = 0; i < 8; i++) {
            const int idx = tid + i * 256;
            const int row = idx >> 4;
            const int ch  = idx & 15;
            cp_async16(sKu + (uint32_t)(row * ATT_KPAD + ch * 4) * 4,
                       Qg + row * 64 + ch * 4);
        }
    }
    CP_COMMIT(); CP_WAIT0();
    __syncthreads();

    uint32_t aq[8][4];
    {
        const int qr = wid * 16;
#pragma unroll
        for (int kb = 0; kb < 8; kb++) {
            aq[kb][0] = __float_as_uint(Ks[(qr + g)     * ATT_KPAD + kb * 8 + t4]);
            aq[kb][1] = __float_as_uint(Ks[(qr + g + 8) * ATT_KPAD + kb * 8 + t4]);
            aq[kb][2] = __float_as_uint(Ks[(qr + g)     * ATT_KPAD + kb * 8 + t4 + 4]);
            aq[kb][3] = __float_as_uint(Ks[(qr + g + 8) * ATT_KPAD + kb * 8 + t4 + 4]);
        }
    }
    __syncthreads();

    const float* Kg = K + base;
    const float* Vg = V + base;
    auto ldkv = [&](int jt) {
        const int slot = jt & 1;
#pragma unroll
        for (int i = 0; i < 4; i++) {
            const int idx = tid + i * 256;
            const int row = idx >> 4;
            const int ch  = idx & 15;
            cp_async16(sKu + (uint32_t)(slot * ATT_KSTG + row * ATT_KPAD + ch * 4) * 4,
                       Kg + (size_t)(jt * 64 + row) * 64 + ch * 4);
            cp_async16(sVu + (uint32_t)(slot * ATT_VSTG + row * ATT_VPAD + ch * 4) * 4,
                       Vg + (size_t)(jt * 64 + row) * 64 + ch * 4);
        }
    };

    ldkv(0); CP_COMMIT();

    float m0 = -INFINITY, m1 = -INFINITY, l0 = 0.f, l1 = 0.f;
    float o[8][4];
#pragma unroll
    for (int nt = 0; nt < 8; nt++)
#pragma unroll
        for (int c = 0; c < 4; c++) o[nt][c] = 0.f;

    for (int jt = 0; jt < Sq / 64; jt++) {
        if (jt + 1 < Sq / 64) { ldkv(jt + 1); CP_COMMIT(); CP_WAIT1(); }
        else                  { CP_WAIT0(); }
        __syncthreads();

        const float* Kt = Ks + (jt & 1) * ATT_KSTG;
        const float* Vt = Vs + (jt & 1) * ATT_VSTG;

        float sc[8][4];
#pragma unroll
        for (int nt = 0; nt < 8; nt++) {
#pragma unroll
            for (int c = 0; c < 4; c++) sc[nt][c] = 0.f;
            const float* kr = Kt + (nt * 8 + g) * ATT_KPAD;
#pragma unroll
            for (int kb = 0; kb < 8; kb++) {
                uint32_t bf[2];
                bf[0] = __float_as_uint(kr[kb * 8 + t4]);
                bf[1] = __float_as_uint(kr[kb * 8 + t4 + 4]);
                mma_tf32(sc[nt], aq[kb], bf);
            }
        }

        float mx0 = -INFINITY, mx1 = -INFINITY;
#pragma unroll
        for (int nt = 0; nt < 8; nt++) {
            mx0 = fmaxf(mx0, fmaxf(sc[nt][0], sc[nt][1]));
            mx1 = fmaxf(mx1, fmaxf(sc[nt][2], sc[nt][3]));
        }
        mx0 = fmaxf(mx0, __shfl_xor_sync(0xffffffffu, mx0, 1));
        mx0 = fmaxf(mx0, __shfl_xor_sync(0xffffffffu, mx0, 2));
        mx1 = fmaxf(mx1, __shfl_xor_sync(0xffffffffu, mx1, 1));
        mx1 = fmaxf(mx1, __shfl_xor_sync(0xffffffffu, mx1, 2));

        const float nm0 = fmaxf(m0, mx0);
        const float nm1 = fmaxf(m1, mx1);
        const float f0 = __expf(m0 - nm0);
        const float f1 = __expf(m1 - nm1);
        float sum0 = 0.f, sum1 = 0.f;
#pragma unroll
        for (int nt = 0; nt < 8; nt++) {
            sc[nt][0] = __expf(sc[nt][0] - nm0);
            sc[nt][1] = __expf(sc[nt][1] - nm0);
            sc[nt][2] = __expf(sc[nt][2] - nm1);
            sc[nt][3] = __expf(sc[nt][3] - nm1);
            sum0 += sc[nt][0] + sc[nt][1];
            sum1 += sc[nt][2] + sc[nt][3];
        }
        sum0 += __shfl_xor_sync(0xffffffffu, sum0, 1);
        sum0 += __shfl_xor_sync(0xffffffffu, sum0, 2);
        sum1 += __shfl_xor_sync(0xffffffffu, sum1, 1);
        sum1 += __shfl_xor_sync(0xffffffffu, sum1, 2);
        l0 = l0 * f0 + sum0;
        l1 = l1 * f1 + sum1;
        m0 = nm0; m1 = nm1;
#pragma unroll
        for (int nt = 0; nt < 8; nt++) {
            o[nt][0] *= f0; o[nt][1] *= f0;
            o[nt][2] *= f1; o[nt][3] *= f1;
        }

        const int qbase = lane & ~3;
        const int src0 = qbase + (t4 >> 1);
        const int src1 = src0 + 2;
        const bool odd = (t4 & 1);
#pragma unroll
        for (int kb = 0; kb < 8; kb++) {
            float s00 = __shfl_sync(0xffffffffu, sc[kb][0], src0);
            float s01 = __shfl_sync(0xffffffffu, sc[kb][1], src0);
            float s02 = __shfl_sync(0xffffffffu, sc[kb][2], src0);
            float s03 = __shfl_sync(0xffffffffu, sc[kb][3], src0);
            float s10 = __shfl_sync(0xffffffffu, sc[kb][0], src1);
            float s11 = __shfl_sync(0xffffffffu, sc[kb][1], src1);
            float s12 = __shfl_sync(0xffffffffu, sc[kb][2], src1);
            float s13 = __shfl_sync(0xffffffffu, sc[kb][3], src1);
            uint32_t ap[4];
            ap[0] = __float_as_uint(odd ? s01 : s00);
            ap[1] = __float_as_uint(odd ? s03 : s02);
            ap[2] = __float_as_uint(odd ? s11 : s10);
            ap[3] = __float_as_uint(odd ? s13 : s12);
            const float* vr0 = Vt + (kb * 8 + t4) * ATT_VPAD;
            const float* vr1 = Vt + (kb * 8 + t4 + 4) * ATT_VPAD;
#pragma unroll
            for (int nt = 0; nt < 8; nt++) {
                uint32_t bf[2];
                bf[0] = __float_as_uint(vr0[nt * 8 + g]);
                bf[1] = __float_as_uint(vr1[nt * 8 + g]);
                mma_tf32(o[nt], ap, bf);
            }
        }
        __syncthreads();
    }

    const float il0 = 1.f / l0;
    const float il1 = 1.f / l1;
    const int row0 = it * 128 + wid * 16 + g;
#pragma unroll
    for (int nt = 0; nt < 8; nt++) {
        const int col = h * Dh + nt * 8 + t4 * 2;
        float2 v0 = make_float2(o[nt][0] * il0, o[nt][1] * il0);
        float2 v1 = make_float2(o[nt][2] * il1, o[nt][3] * il1);
        *(float2*)&ctx[((size_t)b * Sq + row0) * Dq + col]     = v0;
        *(float2*)&ctx[((size_t)b * Sq + row0 + 8) * Dq + col] = v1;
    }
}

// ---------------- LayerNorm(512) + exact GELU, warp per row ----------------
__global__ void __launch_bounds__(256)
ln_gelu_kernel(const float* __restrict__ gamma, const float* __restrict__ beta) {
    const int lane = threadIdx.x & 31;
    const int row  = blockIdx.x * 8 + (threadIdx.x >> 5);
    float* rp = g_y + (size_t)row * 512;

    float4 x[4];
    float s = 0.f, ss = 0.f;
#pragma unroll
    for (int j = 0; j < 4; j++) {
        x[j] = *(const float4*)&rp[lane * 4 + j * 128];
        s  += x[j].x + x[j].y + x[j].z + x[j].w;
        ss += x[j].x * x[j].x + x[j].y * x[j].y + x[j].z * x[j].z + x[j].w * x[j].w;
    }
#pragma unroll
    for (int msk = 16; msk >= 1; msk >>= 1) {
        s  += __shfl_xor_sync(0xffffffffu, s,  msk);
        ss += __shfl_xor_sync(0xffffffffu, ss, msk);
    }
    const float mu  = s * (1.f / 512.f);
    const float var = ss * (1.f / 512.f) - mu * mu;
    const float inv = rsqrtf(var + 1e-5f);

#pragma unroll
    for (int j = 0; j < 4; j++) {
        const int c = lane * 4 + j * 128;
        const float4 gm = *(const float4*)&gamma[c];
        const float4 bt = *(const float4*)&beta[c];
        float4 y;
        y.x = (x[j].x - mu) * inv * gm.x + bt.x;
        y.y = (x[j].y - mu) * inv * gm.y + bt.y;
        y.z = (x[j].z - mu) * inv * gm.z + bt.z;
        y.w = (x[j].w - mu) * inv * gm.w + bt.w;
        y.x = 0.5f * y.x * (1.f + erff(y.x * 0.70710678118654752440f));
        y.y = 0.5f * y.y * (1.f + erff(y.y * 0.70710678118654752440f));
        y.z = 0.5f * y.z * (1.f + erff(y.z * 0.70710678118654752440f));
        y.w = 0.5f * y.w * (1.f + erff(y.w * 0.70710678118654752440f));
        *(float4*)&rp[c] = y;
    }
}

// ---------------- launch ----------------------------------------------------
extern "C" void kernel_launch(void* const* d_in, const int* in_sizes, int n_in,
                              void* d_out, int out_size) {
    const float* desc   = (const float*)d_in[0];
    const float* kp     = (const float*)d_in[1];
    const float* Wqkv_w = (const float*)d_in[2];
    const float* Wqkv_b = (const float*)d_in[3];
    const float* Wo_w   = (const float*)d_in[4];
    const float* Wo_b   = (const float*)d_in[5];
    const float* W1_w   = (const float*)d_in[6];
    const float* W1_b   = (const float*)d_in[7];
    const float* ln_g   = (const float*)d_in[8];
    const float* ln_b   = (const float*)d_in[9];
    const float* W2_w   = (const float*)d_in[10];
    const float* W2_b   = (const float*)d_in[11];
    float* out = (float*)d_out;

    void *p_q, *p_k, *p_v, *p_ctx, *p_msg, *p_y;
    cudaGetSymbolAddress(&p_q,   g_q);
    cudaGetSymbolAddress(&p_k,   g_k);
    cudaGetSymbolAddress(&p_v,   g_v);
    cudaGetSymbolAddress(&p_ctx, g_ctx);
    cudaGetSymbolAddress(&p_msg, g_msg);
    cudaGetSymbolAddress(&p_y,   g_y);

    cudaFuncSetAttribute(qkv_gemm_rope_kernel,
                         cudaFuncAttributeMaxDynamicSharedMemorySize, G_SMEM_TOT);
    cudaFuncSetAttribute(mma_gemm_kernel<false>,
                         cudaFuncAttributeMaxDynamicSharedMemorySize, G_SMEM_TOT);
    cudaFuncSetAttribute(mma_gemm_kernel<true>,
                         cudaFuncAttributeMaxDynamicSharedMemorySize, G_SMEM_TOT);
    cudaFuncSetAttribute(fa_mma_kernel,
                         cudaFuncAttributeMaxDynamicSharedMemorySize, ATT_SMEM);

    // 1) QKV GEMM + RoPE + split -> g_q/g_k/g_v [B,H,S,Dh]
    qkv_gemm_rope_kernel<<<dim3(6, Mq / 128), 256, G_SMEM_TOT>>>(
        desc, Wqkv_w, Wqkv_b, kp);

    // 2) flash attention (tensor-core) -> ctx [B,S,D]
    fa_mma_kernel<<<dim3(Sq / 128, Hq, Bq), 256, ATT_SMEM>>>(
        (const float*)p_q, (const float*)p_k, (const float*)p_v, (float*)p_ctx);

    // 3) message = ctx @ Wo^T + b
    mma_gemm_kernel<false><<<dim3(Dq / 128, Mq / 128), 256, G_SMEM_TOT>>>(
        (const float*)p_ctx, nullptr, Wo_w, Wo_b, nullptr,
        (float*)p_msg, Mq, Dq, Dq, Dq);

    // 4) y = [desc | msg] @ W1^T + b   (virtual concat via split-K loader)
    mma_gemm_kernel<false><<<dim3(512 / 128, Mq / 128), 256, G_SMEM_TOT>>>(
        desc, (const float*)p_msg, W1_w, W1_b, nullptr,
        (float*)p_y, Mq, 512, 512, 256);

    // 5) LayerNorm + GELU (in place, warp per row)
    ln_gelu_kernel<<<Mq / 8, 256>>>(ln_g, ln_b);

    // 6) out = desc + y @ W2^T + b
    mma_gemm_kernel<true><<<dim3(Dq / 128, Mq / 128), 256, G_SMEM_TOT>>>(
        (const float*)p_y, nullptr, W2_w, W2_b, desc, out, Mq, Dq, 512, 512);
}